// round 14
// baseline (speedup 1.0000x reference)
#include <cuda_runtime.h>
#include <cstdint>

// ItemCodeDPQ: out[b,s,m*16+d] = centroids[m, clamp(item_codes[input_ids[b,s], m],0,255), d]
//              zeroed where input_ids[b,s] == 0.  input_ids arrive as int32.
//
// R14 = R13's conflict-free transposed smem table  +  R8's phase-split staging.
//  - table in smem as [code][sub][part]: gather f4idx = code*32 + lane
//    -> every 8 consecutive lanes span all 32 banks: zero LDS conflicts,
//       and gathers run on the smem crossbar, parallel to the L1tex store path.
//  - Phase A stages 16 code ints per warp (16 independent id->code L2 chains
//    in flight; 32 warps/SM * 16 = 512 outstanding -> L2 latency covered).
//  - Phase B: conflict-free LDS + streaming STG per token.

#define CENT_F4 8192   // 8*256*16 floats / 4 = 131072 bytes

__global__ void __launch_bounds__(1024, 1)
itemcode_dpq_kernel(const int* __restrict__ input_ids,
                    const int* __restrict__ item_codes,
                    const float4* __restrict__ centroids4,
                    float4* __restrict__ out4,
                    int ntok)
{
    extern __shared__ float4 s_cent[];   // [256][8][4] = [code][sub][part]

    // cooperative transposed table load:
    // global f4idx = (sub*256 + code)*4 + part -> smem f4idx = code*32 + sub*4 + part
    for (int i = threadIdx.x; i < CENT_F4; i += 1024) {
        const int part = i & 3;
        const int code = (i >> 2) & 255;
        const int sub  = i >> 10;
        s_cent[code * 32 + sub * 4 + part] = centroids4[i];
    }
    __syncthreads();

    const unsigned lane = threadIdx.x & 31u;
    const unsigned sub  = lane >> 2;          // 0..7 : sub-codebook this lane serves

    const unsigned warp   = (blockIdx.x * 1024u + threadIdx.x) >> 5;
    const unsigned nwarp  = gridDim.x * 32u;
    const unsigned nchunk = (unsigned)ntok >> 4;      // ntok divisible by 16

    for (unsigned ch = warp; ch < nchunk; ch += nwarp) {
        const unsigned t0 = ch * 16u;

        // ---- Phase A: 16 independent id -> code chains, stage codes ----
        int c[16];
        unsigned zmask = 0u;
        #pragma unroll
        for (int j = 0; j < 16; j++) {
            const unsigned id = (unsigned)__ldg(&input_ids[t0 + (unsigned)j]);
            c[j] = __ldg(&item_codes[id * 8u + sub]);   // 1 sector/warp/token
            zmask |= (id == 0u) ? (1u << j) : 0u;
        }

        // ---- Phase B: conflict-free LDS gather -> streaming store ----
        #pragma unroll
        for (int j = 0; j < 16; j++) {
            const unsigned code = (unsigned)min(max(c[j], 0), 255);
            float4 v = s_cent[code * 32u + lane];       // zero-conflict by layout
            if ((zmask >> j) & 1u) v = make_float4(0.f, 0.f, 0.f, 0.f);
            __stcs(&out4[(t0 + (unsigned)j) * 32u + lane], v);
        }
    }
}

extern "C" void kernel_launch(void* const* d_in, const int* in_sizes, int n_in,
                              void* d_out, int out_size)
{
    const int*    input_ids  = (const int*)d_in[0];     // (1024,200) int32
    const int*    item_codes = (const int*)d_in[1];     // (1e6, 8) int32
    const float4* centroids  = (const float4*)d_in[2];  // (8,256,16) fp32
    float4*       out        = (float4*)d_out;          // (1024,200,128) fp32

    const int ntok = in_sizes[0];   // 204800

    cudaFuncSetAttribute(itemcode_dpq_kernel,
                         cudaFuncAttributeMaxDynamicSharedMemorySize, 131072);

    int nsm = 148;
    cudaDeviceGetAttribute(&nsm, cudaDevAttrMultiProcessorCount, 0);

    itemcode_dpq_kernel<<<nsm, 1024, 131072>>>(input_ids, item_codes, centroids,
                                               out, ntok);
}

// round 15
// speedup vs baseline: 1.0090x; 1.0090x over previous
#include <cuda_runtime.h>
#include <cuda_fp16.h>
#include <cstdint>

// ItemCodeDPQ: out[b,s,m*16+d] = centroids[m, clamp(item_codes[input_ids[b,s], m],0,255), d]
//              zeroed where input_ids[b,s] == 0.  input_ids arrive as int32.
//
// R15: fp16 table (max rel err 2^-11 = 4.9e-4 < 1e-3 tolerance) so the FULL
// table fits in 64KB smem -> 2 CTAs/SM x 1024 thr = 64 warps/SM (vs 45 best
// so far), while keeping the conflict-free transposed layout:
//   smem half index = code*128 + sub*16 + d  -> lane reads 8B at code*256B +
//   lane*8B: each 16-lane phase spans all 32 banks (zero conflicts, no L1tex
//   gather replays). Pre-kernel converts/transposes the table once per launch.

__device__ __half g_cent_h[8 * 256 * 16];   // 64KB, [code][sub][d]

// ---------------- pre-kernel: fp32 -> fp16 transpose ----------------
__global__ void __launch_bounds__(256)
convert_table_kernel(const float* __restrict__ cent)
{
    const int i = blockIdx.x * 256 + threadIdx.x;    // 0..32767
    if (i >= 8 * 256 * 16) return;
    const int d    = i & 15;
    const int code = (i >> 4) & 255;
    const int sub  = i >> 12;
    g_cent_h[code * 128 + sub * 16 + d] = __float2half_rn(cent[i]);
}

// ---------------- main kernel ----------------
__global__ void __launch_bounds__(1024, 2)
itemcode_dpq_kernel(const int* __restrict__ input_ids,
                    const int* __restrict__ item_codes,
                    float4* __restrict__ out4,
                    int ntok)
{
    extern __shared__ __half s_cent[];   // [256][8][16] halves = 64KB

    // copy fp16 table from device global (L2-hot) into smem: 4096 uint4
    {
        const uint4* src = (const uint4*)g_cent_h;
        uint4*       dst = (uint4*)s_cent;
        #pragma unroll
        for (int i = threadIdx.x; i < 4096; i += 1024)
            dst[i] = src[i];
    }
    __syncthreads();

    const unsigned lane = threadIdx.x & 31u;
    const unsigned sub  = lane >> 2;          // 0..7 : sub-codebook this lane serves

    const unsigned warp   = (blockIdx.x * 1024u + threadIdx.x) >> 5;
    const unsigned nwarp  = gridDim.x * 32u;
    const unsigned nchunk = (unsigned)ntok >> 4;      // ntok divisible by 16

    for (unsigned ch = warp; ch < nchunk; ch += nwarp) {
        const unsigned t0 = ch * 16u;
        #pragma unroll
        for (int j = 0; j < 16; j++) {
            const unsigned t  = t0 + (unsigned)j;
            const unsigned id = (unsigned)__ldg(&input_ids[t]);
            int code = __ldg(&item_codes[id * 8u + sub]);  // 1 sector/warp/token
            code = min(max(code, 0), 255);

            // conflict-free LDS.64: half index = code*128 + lane*4
            const uint2 h4 = *(const uint2*)&s_cent[(unsigned)code * 128u + lane * 4u];
            const float2 f0 = __half22float2(*(const __half2*)&h4.x);
            const float2 f1 = __half22float2(*(const __half2*)&h4.y);
            float4 v = make_float4(f0.x, f0.y, f1.x, f1.y);
            if (id == 0u) v = make_float4(0.f, 0.f, 0.f, 0.f);
            __stcs(&out4[t * 32u + lane], v);
        }
    }
}

extern "C" void kernel_launch(void* const* d_in, const int* in_sizes, int n_in,
                              void* d_out, int out_size)
{
    const int*   input_ids  = (const int*)d_in[0];     // (1024,200) int32
    const int*   item_codes = (const int*)d_in[1];     // (1e6, 8) int32
    const float* centroids  = (const float*)d_in[2];   // (8,256,16) fp32
    float4*      out        = (float4*)d_out;          // (1024,200,128) fp32

    const int ntok = in_sizes[0];   // 204800

    convert_table_kernel<<<(8 * 256 * 16 + 255) / 256, 256>>>(centroids);

    cudaFuncSetAttribute(itemcode_dpq_kernel,
                         cudaFuncAttributeMaxDynamicSharedMemorySize, 65536);

    int nsm = 148;
    cudaDeviceGetAttribute(&nsm, cudaDevAttrMultiProcessorCount, 0);

    // 2 CTAs/SM, 1024 threads each, grid-stride over 16-token chunks
    itemcode_dpq_kernel<<<nsm * 2, 1024, 65536>>>(input_ids, item_codes,
                                                  out, ntok);
}

// round 16
// speedup vs baseline: 1.1091x; 1.0992x over previous
#include <cuda_runtime.h>
#include <cstdint>

// ItemCodeDPQ: out[b,s,m*16+d] = centroids[m, clamp(item_codes[input_ids[b,s], m],0,255), d]
//              zeroed where input_ids[b,s] == 0.  input_ids arrive as int32.
//
// R16 = R6 (best: rolling per-token chains, direct per-lane code LDG,
// L1-resident 128KB fp32 centroid gather, __stcs streaming stores) refined:
//  - persistent grid 148*4 CTAs x 512 thr (64 warps/SM, 100% theoretical occ)
//  - uniform int4 id loads: 4 ids per LDG.128 (fewer L1tex wavefronts)

__global__ void __launch_bounds__(512)
itemcode_dpq_kernel(const int4* __restrict__ input_ids4,
                    const int* __restrict__ item_codes,
                    const float4* __restrict__ centroids4,
                    float4* __restrict__ out4,
                    int ntok)
{
    const unsigned lane = threadIdx.x & 31u;
    const unsigned sub  = lane >> 2;          // 0..7 : sub-codebook this lane serves
    const unsigned part = lane & 3u;          // 0..3 : float4 within 16-float sub-emb

    const unsigned warp   = (blockIdx.x * 512u + threadIdx.x) >> 5;
    const unsigned nwarp  = gridDim.x * 16u;
    const unsigned nchunk = (unsigned)ntok >> 4;      // ntok = 204800, /16

    for (unsigned ch = warp; ch < nchunk; ch += nwarp) {
        const unsigned t0 = ch * 16u;

        #pragma unroll
        for (int q = 0; q < 4; q++) {
            // uniform 16B load: 4 ids for the next 4 tokens (1 wavefront)
            const int4 ids = __ldg(&input_ids4[(t0 >> 2) + (unsigned)q]);

            #pragma unroll
            for (int j = 0; j < 4; j++) {
                const unsigned t  = t0 + (unsigned)(q * 4 + j);
                const unsigned id = (unsigned)((j == 0) ? ids.x :
                                               (j == 1) ? ids.y :
                                               (j == 2) ? ids.z : ids.w);
                // per-lane code load: 8 distinct words/warp = one 32B sector
                int code = __ldg(&item_codes[id * 8u + sub]);
                code = min(max(code, 0), 255);

                float4 v = __ldg(&centroids4[(sub * 256u + (unsigned)code) * 4u + part]);
                if (id == 0u) v = make_float4(0.f, 0.f, 0.f, 0.f);
                __stcs(&out4[t * 32u + lane], v);
            }
        }
    }
}

extern "C" void kernel_launch(void* const* d_in, const int* in_sizes, int n_in,
                              void* d_out, int out_size)
{
    const int4*   input_ids  = (const int4*)d_in[0];    // (1024,200) int32, 16B-aligned
    const int*    item_codes = (const int*)d_in[1];     // (1e6, 8) int32
    const float4* centroids  = (const float4*)d_in[2];  // (8,256,16) fp32
    float4*       out        = (float4*)d_out;          // (1024,200,128) fp32

    const int ntok = in_sizes[0];   // 204800

    int nsm = 148;
    cudaDeviceGetAttribute(&nsm, cudaDevAttrMultiProcessorCount, 0);

    // 4 CTAs/SM x 512 thr = 64 warps/SM; grid-stride over 16-token chunks
    itemcode_dpq_kernel<<<nsm * 4, 512>>>(input_ids, item_codes, centroids,
                                          out, ntok);
}